// round 6
// baseline (speedup 1.0000x reference)
#include <cuda_runtime.h>
#include <cstdint>

// Per-batch class-presence bitmasks (bits 0..5), B=64. Written by presence
// kernel (one warp per batch, plain STG), read by loss kernel. Stream order +
// per-launch L1D flush on sm_103a make plain loads safe.
__device__ unsigned g_masks[64];

// ---------------------------------------------------------------------------
// Presence kernel: grid = B blocks x 32 threads (ONE warp, no smem, no BAR).
// Each warp ORs labels (0..5) of its batch into a 6-bit mask.
// Iter 0 covers 32 int4 = 128 labels: p(any class missing) ~ 6*(5/6)^128
// ~ 4e-10 on uniform data, so the fallback loop almost never runs; presence-OR
// is monotone so early exit is exact, and adversarial data just degrades to a
// full (still correct) scan.
// ---------------------------------------------------------------------------
__global__ void __launch_bounds__(32, 32)
presence_kernel(const int* __restrict__ target, int n_vec4_per_batch) {
    const int lane = threadIdx.x;
    const int4* __restrict__ t4 = reinterpret_cast<const int4*>(target)
                                  + (long long)blockIdx.x * n_vec4_per_batch;

    unsigned acc = 0u;
    if (lane < n_vec4_per_batch) {
        int4 v = t4[lane];
        acc = (1u << (v.x & 31)) | (1u << (v.y & 31)) |
              (1u << (v.z & 31)) | (1u << (v.w & 31));
    }
    acc = __reduce_or_sync(0xffffffffu, acc) & 0x3Fu;

    if (acc != 0x3Fu) {                        // cold path: finish the scan
        for (int base = 32; base < n_vec4_per_batch; base += 32) {
            int idx = base + lane;
            unsigned a = 0u;
            if (idx < n_vec4_per_batch) {
                int4 v = t4[idx];
                a = (1u << (v.x & 31)) | (1u << (v.y & 31)) |
                    (1u << (v.z & 31)) | (1u << (v.w & 31));
            }
            acc |= __reduce_or_sync(0xffffffffu, a) & 0x3Fu;
            if (acc == 0x3Fu) break;
        }
    }

    if (lane == 0) g_masks[blockIdx.x] = acc;
}

// ---------------------------------------------------------------------------
// Loss kernel: 1 block x 384 threads, one per (batch, class) BCE term.
// Log terms clamped at -100 (torch BCELoss semantics). Mean over 384.
// ---------------------------------------------------------------------------
__global__ void __launch_bounds__(384, 1)
loss_kernel(const float* __restrict__ se_pred,
            float* __restrict__ out, int n_terms) {
    const int i = threadIdx.x;           // 0..383
    float v = 0.0f;
    if (i < n_terms) {
        const int b = i / 6;
        const int c = i - b * 6;
        const float p   = se_pred[i];
        const float t   = (float)((g_masks[b] >> c) & 1u);
        const float lp  = fmaxf(logf(p),    -100.0f);
        const float l1p = fmaxf(log1pf(-p), -100.0f);
        v = -(t * lp + (1.0f - t) * l1p);
    }

    // Block reduction: 12 warps -> shared -> warp 0.
    __shared__ float sh[12];
    #pragma unroll
    for (int o = 16; o > 0; o >>= 1) v += __shfl_down_sync(0xffffffffu, v, o);
    if ((i & 31) == 0) sh[i >> 5] = v;
    __syncthreads();
    if (i < 32) {
        float s = (i < 12) ? sh[i] : 0.0f;
        #pragma unroll
        for (int o = 8; o > 0; o >>= 1) s += __shfl_down_sync(0xffffffffu, s, o);
        if (i == 0) out[0] = s / (float)n_terms;
    }
}

// ---------------------------------------------------------------------------
extern "C" void kernel_launch(void* const* d_in, const int* in_sizes, int n_in,
                              void* d_out, int out_size) {
    // Resolve inputs by size: se_pred has 64*6 = 384 elements; target is huge.
    int se_idx = 0, tg_idx = 1;
    if (n_in >= 2 && in_sizes[0] > in_sizes[1]) { se_idx = 1; tg_idx = 0; }

    const float* se_pred = (const float*)d_in[se_idx];
    const int*   target  = (const int*)d_in[tg_idx];
    float* out = (float*)d_out;

    const int n_terms   = in_sizes[se_idx];        // 384
    const int B         = n_terms / 6;             // 64
    const int per_batch = in_sizes[tg_idx] / B;    // 262144 int32 labels
    const int n_vec4    = per_batch / 4;           // int4 count per batch

    presence_kernel<<<B, 32>>>(target, n_vec4);
    loss_kernel<<<1, 384>>>(se_pred, out, n_terms);
}